// round 2
// baseline (speedup 1.0000x reference)
#include <cuda_runtime.h>
#include <stdint.h>

#define D 128
#define MAX_NODES 100000

// Scratch for y = x_out @ W0  (51.2 MB) — device global, no allocation.
__device__ float g_y[MAX_NODES * D];
// edge_index dtype flag: 1 = int64, 0 = int32
__device__ int g_is64;

// ---------------------------------------------------------------------------
// Kernel 0: detect edge_index dtype. True int64 data (values < 2^31) has all
// high 32-bit words zero; int32 index data reinterpreted as int64 has random
// nonzero high words with overwhelming probability.
// ---------------------------------------------------------------------------
__global__ void detect_dtype(const unsigned int* __restrict__ ei_raw, int nwords)
{
    // single block, 256 threads; check first 512 int64 candidates (1024 words)
    __shared__ int bad;
    if (threadIdx.x == 0) bad = 0;
    __syncthreads();
    int limit = 1024;
    if (limit > nwords) limit = nwords & ~1;
    for (int i = threadIdx.x; i * 2 + 1 < limit; i += blockDim.x) {
        unsigned int hi = ei_raw[i * 2 + 1];
        if (hi != 0u) atomicOr(&bad, 1);
    }
    __syncthreads();
    if (threadIdx.x == 0) g_is64 = bad ? 0 : 1;
}

// ---------------------------------------------------------------------------
// Kernel 1: y[n, :] = x_out[n, :] @ W0   (W0 row-major: W0[k*D + c])
// 256 threads -> 32-row x 32-col tile; 4 outputs/thread. grid = (n/32, 4).
// ---------------------------------------------------------------------------
__global__ void __launch_bounds__(256) gemm_xout_w(
    const float* __restrict__ x_out,
    const float* __restrict__ W,
    int n)
{
    __shared__ float As[D * 33];   // transposed: As[k*33 + r]
    __shared__ float Ws[D * 32];   // Ws[k*32 + c]

    const int tid  = threadIdx.x;
    const int row0 = blockIdx.x * 32;
    const int col0 = blockIdx.y * 32;

    #pragma unroll
    for (int i = tid; i < D * 32; i += 256) {
        int k = i >> 5;
        int c = i & 31;
        Ws[i] = W[k * D + col0 + c];
    }

    #pragma unroll
    for (int i = tid; i < 32 * D; i += 256) {
        int r = i >> 7;
        int k = i & (D - 1);
        int gr = row0 + r;
        As[k * 33 + r] = (gr < n) ? x_out[gr * D + k] : 0.0f;
    }
    __syncthreads();

    const int row = tid & 31;
    const int cg  = tid >> 5;
    float acc0 = 0.f, acc1 = 0.f, acc2 = 0.f, acc3 = 0.f;

    #pragma unroll 8
    for (int k = 0; k < D; k++) {
        float a = As[k * 33 + row];
        float4 w = *reinterpret_cast<const float4*>(&Ws[k * 32 + cg * 4]);
        acc0 = fmaf(a, w.x, acc0);
        acc1 = fmaf(a, w.y, acc1);
        acc2 = fmaf(a, w.z, acc2);
        acc3 = fmaf(a, w.w, acc3);
    }

    const int gr = row0 + row;
    if (gr < n) {
        float4 v = make_float4(acc0, acc1, acc2, acc3);
        *reinterpret_cast<float4*>(&g_y[gr * D + col0 + cg * 4]) = v;
    }
}

// ---------------------------------------------------------------------------
// Kernel 2: out[e] = sigmoid( dot( y[src_e], x_in[dst_e] ) )
// One warp per edge; lane handles one float4 chunk of the 128-dim dot.
// ---------------------------------------------------------------------------
__global__ void __launch_bounds__(256) edge_bilinear(
    const float* __restrict__ x_in,
    const void* __restrict__ ei,     // [2, E], int32 or int64 per g_is64
    float* __restrict__ out,
    int E)
{
    const long long gthread = (long long)blockIdx.x * blockDim.x + threadIdx.x;
    const int e    = (int)(gthread >> 5);
    const int lane = threadIdx.x & 31;
    if (e >= E) return;

    long long s, d;
    if (g_is64) {
        const long long* p = (const long long*)ei;
        s = p[e];
        d = p[(long long)E + e];
    } else {
        const int* p = (const int*)ei;
        s = p[e];
        d = p[E + e];
    }

    const float4 a = reinterpret_cast<const float4*>(g_y  + s * D)[lane];
    const float4 b = reinterpret_cast<const float4*>(x_in + d * D)[lane];

    float v = a.x * b.x + a.y * b.y + a.z * b.z + a.w * b.w;

    #pragma unroll
    for (int o = 16; o > 0; o >>= 1)
        v += __shfl_xor_sync(0xFFFFFFFFu, v, o);

    if (lane == 0)
        out[e] = 1.0f / (1.0f + __expf(-v));
}

// ---------------------------------------------------------------------------
// Launch. Identify inputs by element count (robust to metadata order):
//   two equal large f32 arrays (N*D): first = x_in, second = x_out
//   D*D (=16384): W       2*E (largest after pairing): edge_index
// Output: float32 [E].
// ---------------------------------------------------------------------------
extern "C" void kernel_launch(void* const* d_in, const int* in_sizes, int n_in,
                              void* d_out, int out_size)
{
    // defaults per expected metadata order
    int i_xin = 0, i_xout = 1, i_ei = 2, i_w = 3;

    // robust identification
    if (n_in == 4) {
        int w_idx = -1, ei_idx = -1;
        for (int i = 0; i < 4; i++) {
            if (in_sizes[i] == D * D) w_idx = i;
        }
        // edge_index: the remaining array that is not one of the two equal node arrays
        // find pair of equal sizes among the non-W entries
        int idx[3], c = 0;
        for (int i = 0; i < 4; i++) if (i != w_idx) idx[c++] = i;
        if (w_idx >= 0 && c == 3) {
            // find the two equal ones
            if (in_sizes[idx[0]] == in_sizes[idx[1]]) { i_xin = idx[0]; i_xout = idx[1]; ei_idx = idx[2]; }
            else if (in_sizes[idx[0]] == in_sizes[idx[2]]) { i_xin = idx[0]; i_xout = idx[2]; ei_idx = idx[1]; }
            else { i_xin = idx[1]; i_xout = idx[2]; ei_idx = idx[0]; }
            i_w = w_idx; i_ei = ei_idx;
        }
    }

    const float* x_in  = (const float*)d_in[i_xin];
    const float* x_out = (const float*)d_in[i_xout];
    const void*  ei    = d_in[i_ei];
    const float* W     = (const float*)d_in[i_w];
    float*       out   = (float*)d_out;

    int n = in_sizes[i_xin] / D;
    if (n > MAX_NODES) n = MAX_NODES;
    int E = in_sizes[i_ei] / 2;

    // dtype detection (int32 vs int64) — graph-capturable, deterministic
    detect_dtype<<<1, 256>>>((const unsigned int*)ei, in_sizes[i_ei] * 2);

    // y = x_out @ W0
    {
        dim3 grid((n + 31) / 32, 4);
        gemm_xout_w<<<grid, 256>>>(x_out, W, n);
    }

    // per-edge bilinear dot + sigmoid
    {
        long long total_threads = (long long)E * 32;
        int blocks = (int)((total_threads + 255) / 256);
        edge_bilinear<<<blocks, 256>>>(x_in, ei, out, E);
    }
}

// round 3
// speedup vs baseline: 1.0459x; 1.0459x over previous
#include <cuda_runtime.h>
#include <stdint.h>

#define D 128
#define MAX_NODES 100000

// Scratch for y = x_out @ W0  (51.2 MB) — device global, no allocation.
__device__ float g_y[MAX_NODES * D];
// edge_index dtype flag: 1 = int64, 0 = int32
__device__ int g_is64;

// ---------------------------------------------------------------------------
// Kernel 0: detect edge_index dtype (int32 silently produced by JAX x32 mode).
// ---------------------------------------------------------------------------
__global__ void detect_dtype(const unsigned int* __restrict__ ei_raw, int nwords)
{
    __shared__ int bad;
    if (threadIdx.x == 0) bad = 0;
    __syncthreads();
    int limit = 1024;
    if (limit > nwords) limit = nwords & ~1;
    for (int i = threadIdx.x; i * 2 + 1 < limit; i += blockDim.x) {
        unsigned int hi = ei_raw[i * 2 + 1];
        if (hi != 0u) atomicOr(&bad, 1);
    }
    __syncthreads();
    if (threadIdx.x == 0) g_is64 = bad ? 0 : 1;
}

// ---------------------------------------------------------------------------
// Kernel 1: y = x_out @ W0 using packed fp32 FMA (fma.rn.f32x2 -> FFMA2).
// Tile: 64 rows x 128 cols, K staged in chunks of 32. 512 threads.
// Thread (row = tid&63, cg = tid>>6) computes 16 outputs = 8 f32x2 pairs.
// ---------------------------------------------------------------------------
#define BM 64
#define BK 32
#define AS_STRIDE 65   // odd stride -> conflict-free STS (k by lane) and LDS (row by lane)

__global__ void __launch_bounds__(512) gemm_xout_w(
    const float* __restrict__ x_out,
    const float* __restrict__ W,   // [D*D] row-major W[k*D + c]
    int n)
{
    __shared__ float As[BK * AS_STRIDE];      // As[k*65 + r], 8.3 KB
    __shared__ float Ws[BK * D];              // Ws[k*128 + c], 16 KB

    const int tid  = threadIdx.x;
    const int row0 = blockIdx.x * BM;
    const int row  = tid & (BM - 1);
    const int cg   = tid >> 6;                // 0..7 -> cols cg*16 .. cg*16+15
    const int gr   = row0 + row;

    unsigned long long acc[8];
    #pragma unroll
    for (int j = 0; j < 8; j++) acc[j] = 0ull;  // (0.f, 0.f) pairs

    for (int k0 = 0; k0 < D; k0 += BK) {
        // stage A: 32k x 64r = 2048 floats, 4 per thread, coalesced on k
        #pragma unroll
        for (int i = tid; i < BK * BM; i += 512) {
            int k = i & (BK - 1);
            int r = i >> 5;
            int grr = row0 + r;
            As[k * AS_STRIDE + r] = (grr < n) ? __ldcs(&x_out[(long long)grr * D + k0 + k]) : 0.0f;
        }
        // stage W slice: 32k x 128c = 4096 floats = 1024 float4
        #pragma unroll
        for (int i4 = tid; i4 < (BK * D) / 4; i4 += 512) {
            int k  = i4 >> 5;
            int c4 = i4 & 31;
            ((float4*)Ws)[i4] = *reinterpret_cast<const float4*>(&W[(k0 + k) * D + c4 * 4]);
        }
        __syncthreads();

        #pragma unroll
        for (int kk = 0; kk < BK; kk++) {
            float a = As[kk * AS_STRIDE + row];
            unsigned long long aa;
            asm("mov.b64 %0, {%1, %1};" : "=l"(aa) : "r"(__float_as_uint(a)));
            const ulonglong2* wp = reinterpret_cast<const ulonglong2*>(&Ws[kk * D + cg * 16]);
            ulonglong2 u0 = wp[0];   // cols +0..3  (2 pairs)
            ulonglong2 u1 = wp[1];   // cols +4..7
            ulonglong2 u2 = wp[2];   // cols +8..11
            ulonglong2 u3 = wp[3];   // cols +12..15
            asm("fma.rn.f32x2 %0, %1, %2, %0;" : "+l"(acc[0]) : "l"(aa), "l"(u0.x));
            asm("fma.rn.f32x2 %0, %1, %2, %0;" : "+l"(acc[1]) : "l"(aa), "l"(u0.y));
            asm("fma.rn.f32x2 %0, %1, %2, %0;" : "+l"(acc[2]) : "l"(aa), "l"(u1.x));
            asm("fma.rn.f32x2 %0, %1, %2, %0;" : "+l"(acc[3]) : "l"(aa), "l"(u1.y));
            asm("fma.rn.f32x2 %0, %1, %2, %0;" : "+l"(acc[4]) : "l"(aa), "l"(u2.x));
            asm("fma.rn.f32x2 %0, %1, %2, %0;" : "+l"(acc[5]) : "l"(aa), "l"(u2.y));
            asm("fma.rn.f32x2 %0, %1, %2, %0;" : "+l"(acc[6]) : "l"(aa), "l"(u3.x));
            asm("fma.rn.f32x2 %0, %1, %2, %0;" : "+l"(acc[7]) : "l"(aa), "l"(u3.y));
        }
        __syncthreads();
    }

    if (gr < n) {
        float* dst = g_y + (long long)gr * D + cg * 16;
        #pragma unroll
        for (int q = 0; q < 4; q++) {
            unsigned int l0, h0, l1, h1;
            asm("mov.b64 {%0, %1}, %2;" : "=r"(l0), "=r"(h0) : "l"(acc[2 * q]));
            asm("mov.b64 {%0, %1}, %2;" : "=r"(l1), "=r"(h1) : "l"(acc[2 * q + 1]));
            float4 v = make_float4(__uint_as_float(l0), __uint_as_float(h0),
                                   __uint_as_float(l1), __uint_as_float(h1));
            *reinterpret_cast<float4*>(dst + q * 4) = v;   // default: leave L2-resident
        }
    }
}

// ---------------------------------------------------------------------------
// Kernel 2: out[e] = sigmoid( dot( y[src_e], x_in[dst_e] ) )
// One warp per edge. Streaming data (indices, out) uses evict-first hints so
// the two 51 MB gather tables stay resident in L2.
// ---------------------------------------------------------------------------
__global__ void __launch_bounds__(256) edge_bilinear(
    const float* __restrict__ x_in,
    const void* __restrict__ ei,     // [2, E]
    float* __restrict__ out,
    int E)
{
    const long long gthread = (long long)blockIdx.x * blockDim.x + threadIdx.x;
    const int e    = (int)(gthread >> 5);
    const int lane = threadIdx.x & 31;
    if (e >= E) return;

    long long s, d;
    if (g_is64) {
        const long long* p = (const long long*)ei;
        s = __ldcs(&p[e]);
        d = __ldcs(&p[(long long)E + e]);
    } else {
        const int* p = (const int*)ei;
        s = __ldcs(&p[e]);
        d = __ldcs(&p[E + e]);
    }

    const float4 a = reinterpret_cast<const float4*>(g_y  + s * D)[lane];
    const float4 b = reinterpret_cast<const float4*>(x_in + d * D)[lane];

    float v = a.x * b.x + a.y * b.y + a.z * b.z + a.w * b.w;

    #pragma unroll
    for (int o = 16; o > 0; o >>= 1)
        v += __shfl_xor_sync(0xFFFFFFFFu, v, o);

    if (lane == 0)
        __stcs(&out[e], 1.0f / (1.0f + __expf(-v)));
}

// ---------------------------------------------------------------------------
// Launch. Identify inputs by element count (robust to metadata order).
// ---------------------------------------------------------------------------
extern "C" void kernel_launch(void* const* d_in, const int* in_sizes, int n_in,
                              void* d_out, int out_size)
{
    int i_xin = 0, i_xout = 1, i_ei = 2, i_w = 3;

    if (n_in == 4) {
        int w_idx = -1, ei_idx = -1;
        for (int i = 0; i < 4; i++)
            if (in_sizes[i] == D * D) w_idx = i;
        int idx[3], c = 0;
        for (int i = 0; i < 4; i++) if (i != w_idx) idx[c++] = i;
        if (w_idx >= 0 && c == 3) {
            if (in_sizes[idx[0]] == in_sizes[idx[1]])      { i_xin = idx[0]; i_xout = idx[1]; ei_idx = idx[2]; }
            else if (in_sizes[idx[0]] == in_sizes[idx[2]]) { i_xin = idx[0]; i_xout = idx[2]; ei_idx = idx[1]; }
            else                                            { i_xin = idx[1]; i_xout = idx[2]; ei_idx = idx[0]; }
            i_w = w_idx; i_ei = ei_idx;
        }
    }

    const float* x_in  = (const float*)d_in[i_xin];
    const float* x_out = (const float*)d_in[i_xout];
    const void*  ei    = d_in[i_ei];
    const float* W     = (const float*)d_in[i_w];
    float*       out   = (float*)d_out;

    int n = in_sizes[i_xin] / D;
    if (n > MAX_NODES) n = MAX_NODES;
    int E = in_sizes[i_ei] / 2;

    detect_dtype<<<1, 256>>>((const unsigned int*)ei, in_sizes[i_ei] * 2);

    {
        dim3 grid((n + BM - 1) / BM);
        gemm_xout_w<<<grid, 512>>>(x_out, W, n);
    }

    {
        long long total_threads = (long long)E * 32;
        int blocks = (int)((total_threads + 255) / 256);
        edge_bilinear<<<blocks, 256>>>(x_in, ei, out, E);
    }
}

// round 5
// speedup vs baseline: 1.3899x; 1.3289x over previous
#include <cuda_runtime.h>
#include <stdint.h>

#define D 128
#define MAX_NODES 100000

// Scratch for y = x_out @ W0  (51.2 MB) — device global, no allocation.
__device__ float g_y[MAX_NODES * D];
// nonzero -> edge_index is int32 (JAX x32 silently downcasts the ref's int64)
__device__ int g_bad;

// ---------------------------------------------------------------------------
// 256-bit evict-last helpers (sm_103a ptxas requires v8.b32/v4.b64 with
// L2::evict_last)
// ---------------------------------------------------------------------------
__device__ __forceinline__ void ldg_el32B(const float* p, float4& lo, float4& hi) {
    unsigned long long x0, x1, x2, x3;
    asm volatile("ld.global.nc.L2::evict_last.v4.b64 {%0,%1,%2,%3}, [%4];"
                 : "=l"(x0), "=l"(x1), "=l"(x2), "=l"(x3) : "l"(p));
    lo.x = __uint_as_float((unsigned)x0); lo.y = __uint_as_float((unsigned)(x0 >> 32));
    lo.z = __uint_as_float((unsigned)x1); lo.w = __uint_as_float((unsigned)(x1 >> 32));
    hi.x = __uint_as_float((unsigned)x2); hi.y = __uint_as_float((unsigned)(x2 >> 32));
    hi.z = __uint_as_float((unsigned)x3); hi.w = __uint_as_float((unsigned)(x3 >> 32));
}
__device__ __forceinline__ void stg_el32B(float* p, unsigned long long x0,
                                          unsigned long long x1,
                                          unsigned long long x2,
                                          unsigned long long x3) {
    asm volatile("st.global.L2::evict_last.v4.b64 [%0], {%1,%2,%3,%4};"
                 :: "l"(p), "l"(x0), "l"(x1), "l"(x2), "l"(x3) : "memory");
}

// ---------------------------------------------------------------------------
// Kernel 1 (FIRST graph node -> ncu sample): y = x_out @ W0, FFMA2.
// Tile 64x128, BK=32, 512 threads, 16 outputs/thread as 8 packed pairs.
// ---------------------------------------------------------------------------
#define BM 64
#define BK 32
#define AS_STRIDE 65

__global__ void __launch_bounds__(512) gemm_xout_w(
    const float* __restrict__ x_out,
    const float* __restrict__ W,   // [D*D] row-major W[k*D + c]
    int n)
{
    __shared__ float As[BK * AS_STRIDE];
    __shared__ float Ws[BK * D];

    const int tid  = threadIdx.x;
    const int row0 = blockIdx.x * BM;
    const int row  = tid & (BM - 1);
    const int cg   = tid >> 6;
    const int gr   = row0 + row;

    unsigned long long acc[8];
    #pragma unroll
    for (int j = 0; j < 8; j++) acc[j] = 0ull;

    for (int k0 = 0; k0 < D; k0 += BK) {
        #pragma unroll
        for (int i = tid; i < BK * BM; i += 512) {
            int k = i & (BK - 1);
            int r = i >> 5;
            int grr = row0 + r;
            As[k * AS_STRIDE + r] = (grr < n) ? __ldcs(&x_out[(long long)grr * D + k0 + k]) : 0.0f;
        }
        #pragma unroll
        for (int i4 = tid; i4 < (BK * D) / 4; i4 += 512) {
            int k  = i4 >> 5;
            int c4 = i4 & 31;
            ((float4*)Ws)[i4] = *reinterpret_cast<const float4*>(&W[(k0 + k) * D + c4 * 4]);
        }
        __syncthreads();

        #pragma unroll
        for (int kk = 0; kk < BK; kk++) {
            float a = As[kk * AS_STRIDE + row];
            unsigned long long aa;
            asm("mov.b64 %0, {%1, %1};" : "=l"(aa) : "r"(__float_as_uint(a)));
            const ulonglong2* wp = reinterpret_cast<const ulonglong2*>(&Ws[kk * D + cg * 16]);
            ulonglong2 u0 = wp[0];
            ulonglong2 u1 = wp[1];
            ulonglong2 u2 = wp[2];
            ulonglong2 u3 = wp[3];
            asm("fma.rn.f32x2 %0, %1, %2, %0;" : "+l"(acc[0]) : "l"(aa), "l"(u0.x));
            asm("fma.rn.f32x2 %0, %1, %2, %0;" : "+l"(acc[1]) : "l"(aa), "l"(u0.y));
            asm("fma.rn.f32x2 %0, %1, %2, %0;" : "+l"(acc[2]) : "l"(aa), "l"(u1.x));
            asm("fma.rn.f32x2 %0, %1, %2, %0;" : "+l"(acc[3]) : "l"(aa), "l"(u1.y));
            asm("fma.rn.f32x2 %0, %1, %2, %0;" : "+l"(acc[4]) : "l"(aa), "l"(u2.x));
            asm("fma.rn.f32x2 %0, %1, %2, %0;" : "+l"(acc[5]) : "l"(aa), "l"(u2.y));
            asm("fma.rn.f32x2 %0, %1, %2, %0;" : "+l"(acc[6]) : "l"(aa), "l"(u3.x));
            asm("fma.rn.f32x2 %0, %1, %2, %0;" : "+l"(acc[7]) : "l"(aa), "l"(u3.y));
        }
        __syncthreads();
    }

    if (gr < n) {
        float* dst = g_y + (long long)gr * D + cg * 16;
        // acc[] is already packed f32 pairs: two 32B evict-last stores
        stg_el32B(dst,     acc[0], acc[1], acc[2], acc[3]);
        stg_el32B(dst + 8, acc[4], acc[5], acc[6], acc[7]);
    }
}

// ---------------------------------------------------------------------------
// Kernel 2: dtype detection (tiny; between gemm and edge kernel).
// ---------------------------------------------------------------------------
__global__ void detect_dtype(const unsigned int* __restrict__ ei_raw, int nwords)
{
    __shared__ int bad;
    if (threadIdx.x == 0) bad = 0;
    __syncthreads();
    int limit = 1024;
    if (limit > nwords) limit = nwords & ~1;
    for (int i = threadIdx.x; i * 2 + 1 < limit; i += blockDim.x) {
        if (ei_raw[i * 2 + 1] != 0u) atomicOr(&bad, 1);
    }
    __syncthreads();
    if (threadIdx.x == 0) g_bad = bad;
}

// ---------------------------------------------------------------------------
// Kernel 3: out[e] = sigmoid( dot( y[src_e], x_in[dst_e] ) )
// One warp = 2 edges; 16 lanes/edge; each lane loads 32B (8 floats) of each
// row with evict-last. Streams use evict-first.
// ---------------------------------------------------------------------------
__global__ void __launch_bounds__(256) edge_bilinear(
    const float* __restrict__ x_in,
    const void* __restrict__ ei,     // [2, E]
    float* __restrict__ out,
    int E)
{
    const unsigned int gthread = blockIdx.x * blockDim.x + threadIdx.x;
    const int warp_id = (int)(gthread >> 5);
    const int lane = threadIdx.x & 31;
    const int half = lane >> 4;          // which edge within the warp
    const int sub  = lane & 15;          // 16 lanes per edge
    const int e    = warp_id * 2 + half;
    if (e >= E) return;

    long long s, d;
    if (g_bad) {                         // int32 indices
        const int* p = (const int*)ei;
        s = __ldcs(&p[e]);
        d = __ldcs(&p[E + e]);
    } else {                             // true int64
        const long long* p = (const long long*)ei;
        s = __ldcs(&p[e]);
        d = __ldcs(&p[(long long)E + e]);
    }

    float4 a0, a1, b0, b1;
    ldg_el32B(g_y  + s * D + sub * 8, a0, a1);
    ldg_el32B(x_in + d * D + sub * 8, b0, b1);

    float v = a0.x * b0.x + a0.y * b0.y + a0.z * b0.z + a0.w * b0.w
            + a1.x * b1.x + a1.y * b1.y + a1.z * b1.z + a1.w * b1.w;

    #pragma unroll
    for (int o = 8; o > 0; o >>= 1)
        v += __shfl_xor_sync(0xFFFFFFFFu, v, o);

    if (sub == 0)
        __stcs(&out[e], 1.0f / (1.0f + __expf(-v)));
}

// ---------------------------------------------------------------------------
// Launch. Identify inputs by element count (robust to metadata order).
// ---------------------------------------------------------------------------
extern "C" void kernel_launch(void* const* d_in, const int* in_sizes, int n_in,
                              void* d_out, int out_size)
{
    int i_xin = 0, i_xout = 1, i_ei = 2, i_w = 3;

    if (n_in == 4) {
        int w_idx = -1, ei_idx = -1;
        for (int i = 0; i < 4; i++)
            if (in_sizes[i] == D * D) w_idx = i;
        int idx[3], c = 0;
        for (int i = 0; i < 4; i++) if (i != w_idx) idx[c++] = i;
        if (w_idx >= 0 && c == 3) {
            if (in_sizes[idx[0]] == in_sizes[idx[1]])      { i_xin = idx[0]; i_xout = idx[1]; ei_idx = idx[2]; }
            else if (in_sizes[idx[0]] == in_sizes[idx[2]]) { i_xin = idx[0]; i_xout = idx[2]; ei_idx = idx[1]; }
            else                                            { i_xin = idx[1]; i_xout = idx[2]; ei_idx = idx[0]; }
            i_w = w_idx; i_ei = ei_idx;
        }
    }

    const float* x_in  = (const float*)d_in[i_xin];
    const float* x_out = (const float*)d_in[i_xout];
    const void*  ei    = d_in[i_ei];
    const float* W     = (const float*)d_in[i_w];
    float*       out   = (float*)d_out;

    int n = in_sizes[i_xin] / D;
    if (n > MAX_NODES) n = MAX_NODES;
    int E = in_sizes[i_ei] / 2;

    {
        dim3 grid((n + BM - 1) / BM);
        gemm_xout_w<<<grid, 512>>>(x_out, W, n);
    }

    detect_dtype<<<1, 256>>>((const unsigned int*)ei, in_sizes[i_ei] * 2);

    {
        // one warp per 2 edges
        long long total_threads = ((long long)E + 1) / 2 * 32;
        int blocks = (int)((total_threads + 255) / 256);
        edge_bilinear<<<blocks, 256>>>(x_in, ei, out, E);
    }
}

// round 6
// speedup vs baseline: 1.6589x; 1.1935x over previous
#include <cuda_runtime.h>
#include <stdint.h>

#define D 128
#define MAX_NODES 100000

// Scratch for y = x_out @ W0  (51.2 MB) — device global, no allocation.
__device__ float g_y[MAX_NODES * D];
// nonzero -> edge_index is int32 (JAX x32 silently downcasts the ref's int64)
__device__ int g_bad;

// ---------------------------------------------------------------------------
// 256-bit evict-last helpers (sm_103a ptxas requires v4.b64 with evict_last)
// ---------------------------------------------------------------------------
__device__ __forceinline__ void ldg_el32B(const float* p, float4& lo, float4& hi) {
    unsigned long long x0, x1, x2, x3;
    asm volatile("ld.global.nc.L2::evict_last.v4.b64 {%0,%1,%2,%3}, [%4];"
                 : "=l"(x0), "=l"(x1), "=l"(x2), "=l"(x3) : "l"(p));
    lo.x = __uint_as_float((unsigned)x0); lo.y = __uint_as_float((unsigned)(x0 >> 32));
    lo.z = __uint_as_float((unsigned)x1); lo.w = __uint_as_float((unsigned)(x1 >> 32));
    hi.x = __uint_as_float((unsigned)x2); hi.y = __uint_as_float((unsigned)(x2 >> 32));
    hi.z = __uint_as_float((unsigned)x3); hi.w = __uint_as_float((unsigned)(x3 >> 32));
}
__device__ __forceinline__ void stg_el32B(float* p, unsigned long long x0,
                                          unsigned long long x1,
                                          unsigned long long x2,
                                          unsigned long long x3) {
    asm volatile("st.global.L2::evict_last.v4.b64 [%0], {%1,%2,%3,%4};"
                 :: "l"(p), "l"(x0), "l"(x1), "l"(x2), "l"(x3) : "memory");
}

// ---------------------------------------------------------------------------
// Kernel 1: y = x_out @ W0, FFMA2, register-blocked 2 rows x 16 cols/thread.
// Tile 128x128, BK=32, 512 threads. Register prefetch hides staging latency.
// ---------------------------------------------------------------------------
#define BM 128
#define BK 32
#define AS_STRIDE 129   // odd -> conflict-free for both STS(k by lane) & LDS(r by lane)

__global__ void __launch_bounds__(512) gemm_xout_w(
    const float* __restrict__ x_out,
    const float* __restrict__ W,   // [D*D] row-major W[k*D + c]
    int n)
{
    __shared__ float As[BK * AS_STRIDE];   // As[k*129 + r], 16.5 KB
    __shared__ float Ws[BK * D];           // Ws[k*128 + c], 16 KB

    const int tid  = threadIdx.x;
    const int row0 = blockIdx.x * BM;
    const int r0   = tid & 63;             // rows r0 and r0+64
    const int cg   = tid >> 6;             // cols cg*16 .. cg*16+15
    const int kA   = tid & 31;             // A staging: fixed k per thread
    const int rA   = tid >> 5;             // A staging: base row per thread

    unsigned long long acc[16];
    #pragma unroll
    for (int j = 0; j < 16; j++) acc[j] = 0ull;

    float  a_pref[8];
    float4 w_pref[2];

    // prefetch tile 0
    #pragma unroll
    for (int j = 0; j < 8; j++) {
        int r = rA + j * 16;
        int grr = row0 + r;
        a_pref[j] = (grr < n) ? __ldcs(&x_out[(size_t)grr * D + kA]) : 0.0f;
    }
    #pragma unroll
    for (int j = 0; j < 2; j++) {
        int k = (tid >> 5) + j * 16;
        w_pref[j] = *reinterpret_cast<const float4*>(&W[k * D + (tid & 31) * 4]);
    }

    #pragma unroll
    for (int t = 0; t < 4; t++) {
        __syncthreads();
        // store prefetched tile to smem
        #pragma unroll
        for (int j = 0; j < 8; j++)
            As[kA * AS_STRIDE + rA + j * 16] = a_pref[j];
        #pragma unroll
        for (int j = 0; j < 2; j++)
            ((float4*)Ws)[tid + j * 512] = w_pref[j];
        __syncthreads();

        // prefetch next tile (overlaps with compute below)
        if (t < 3) {
            int k0 = (t + 1) * BK;
            #pragma unroll
            for (int j = 0; j < 8; j++) {
                int r = rA + j * 16;
                int grr = row0 + r;
                a_pref[j] = (grr < n) ? __ldcs(&x_out[(size_t)grr * D + k0 + kA]) : 0.0f;
            }
            #pragma unroll
            for (int j = 0; j < 2; j++) {
                int k = (tid >> 5) + j * 16;
                w_pref[j] = *reinterpret_cast<const float4*>(&W[(k0 + k) * D + (tid & 31) * 4]);
            }
        }

        #pragma unroll
        for (int kk = 0; kk < BK; kk++) {
            float a0 = As[kk * AS_STRIDE + r0];
            float a1 = As[kk * AS_STRIDE + r0 + 64];
            unsigned long long aa0, aa1;
            asm("mov.b64 %0, {%1, %1};" : "=l"(aa0) : "r"(__float_as_uint(a0)));
            asm("mov.b64 %0, {%1, %1};" : "=l"(aa1) : "r"(__float_as_uint(a1)));
            const ulonglong2* wp = reinterpret_cast<const ulonglong2*>(&Ws[kk * D + cg * 16]);
            ulonglong2 u0 = wp[0];
            ulonglong2 u1 = wp[1];
            ulonglong2 u2 = wp[2];
            ulonglong2 u3 = wp[3];
            asm("fma.rn.f32x2 %0, %1, %2, %0;" : "+l"(acc[0])  : "l"(aa0), "l"(u0.x));
            asm("fma.rn.f32x2 %0, %1, %2, %0;" : "+l"(acc[1])  : "l"(aa0), "l"(u0.y));
            asm("fma.rn.f32x2 %0, %1, %2, %0;" : "+l"(acc[2])  : "l"(aa0), "l"(u1.x));
            asm("fma.rn.f32x2 %0, %1, %2, %0;" : "+l"(acc[3])  : "l"(aa0), "l"(u1.y));
            asm("fma.rn.f32x2 %0, %1, %2, %0;" : "+l"(acc[4])  : "l"(aa0), "l"(u2.x));
            asm("fma.rn.f32x2 %0, %1, %2, %0;" : "+l"(acc[5])  : "l"(aa0), "l"(u2.y));
            asm("fma.rn.f32x2 %0, %1, %2, %0;" : "+l"(acc[6])  : "l"(aa0), "l"(u3.x));
            asm("fma.rn.f32x2 %0, %1, %2, %0;" : "+l"(acc[7])  : "l"(aa0), "l"(u3.y));
            asm("fma.rn.f32x2 %0, %1, %2, %0;" : "+l"(acc[8])  : "l"(aa1), "l"(u0.x));
            asm("fma.rn.f32x2 %0, %1, %2, %0;" : "+l"(acc[9])  : "l"(aa1), "l"(u0.y));
            asm("fma.rn.f32x2 %0, %1, %2, %0;" : "+l"(acc[10]) : "l"(aa1), "l"(u1.x));
            asm("fma.rn.f32x2 %0, %1, %2, %0;" : "+l"(acc[11]) : "l"(aa1), "l"(u1.y));
            asm("fma.rn.f32x2 %0, %1, %2, %0;" : "+l"(acc[12]) : "l"(aa1), "l"(u2.x));
            asm("fma.rn.f32x2 %0, %1, %2, %0;" : "+l"(acc[13]) : "l"(aa1), "l"(u2.y));
            asm("fma.rn.f32x2 %0, %1, %2, %0;" : "+l"(acc[14]) : "l"(aa1), "l"(u3.x));
            asm("fma.rn.f32x2 %0, %1, %2, %0;" : "+l"(acc[15]) : "l"(aa1), "l"(u3.y));
        }
    }

    const int gr0 = row0 + r0;
    const int gr1 = gr0 + 64;
    if (gr0 < n) {
        float* dst = g_y + (size_t)gr0 * D + cg * 16;
        stg_el32B(dst,     acc[0], acc[1], acc[2],  acc[3]);
        stg_el32B(dst + 8, acc[4], acc[5], acc[6],  acc[7]);
    }
    if (gr1 < n) {
        float* dst = g_y + (size_t)gr1 * D + cg * 16;
        stg_el32B(dst,     acc[8],  acc[9],  acc[10], acc[11]);
        stg_el32B(dst + 8, acc[12], acc[13], acc[14], acc[15]);
    }
}

// ---------------------------------------------------------------------------
// Kernel 2: dtype detection (tiny; between gemm and edge kernel).
// ---------------------------------------------------------------------------
__global__ void detect_dtype(const unsigned int* __restrict__ ei_raw, int nwords)
{
    __shared__ int bad;
    if (threadIdx.x == 0) bad = 0;
    __syncthreads();
    int limit = 1024;
    if (limit > nwords) limit = nwords & ~1;
    for (int i = threadIdx.x; i * 2 + 1 < limit; i += blockDim.x) {
        if (ei_raw[i * 2 + 1] != 0u) atomicOr(&bad, 1);
    }
    __syncthreads();
    if (threadIdx.x == 0) g_bad = bad;
}

// ---------------------------------------------------------------------------
// Kernel 3: out[e] = sigmoid( dot( y[src_e], x_in[dst_e] ) )
// One warp = 2 edges; 16 lanes/edge; 32B evict-last gathers (tables pinned
// in L2); streams evict-first. At the L2 LTS cap — leave unchanged.
// ---------------------------------------------------------------------------
__global__ void __launch_bounds__(256) edge_bilinear(
    const float* __restrict__ x_in,
    const void* __restrict__ ei,     // [2, E]
    float* __restrict__ out,
    int E)
{
    const unsigned int gthread = blockIdx.x * blockDim.x + threadIdx.x;
    const int warp_id = (int)(gthread >> 5);
    const int lane = threadIdx.x & 31;
    const int half = lane >> 4;
    const int sub  = lane & 15;
    const int e    = warp_id * 2 + half;
    if (e >= E) return;

    long long s, d;
    if (g_bad) {
        const int* p = (const int*)ei;
        s = __ldcs(&p[e]);
        d = __ldcs(&p[E + e]);
    } else {
        const long long* p = (const long long*)ei;
        s = __ldcs(&p[e]);
        d = __ldcs(&p[(long long)E + e]);
    }

    float4 a0, a1, b0, b1;
    ldg_el32B(g_y  + s * D + sub * 8, a0, a1);
    ldg_el32B(x_in + d * D + sub * 8, b0, b1);

    float v = a0.x * b0.x + a0.y * b0.y + a0.z * b0.z + a0.w * b0.w
            + a1.x * b1.x + a1.y * b1.y + a1.z * b1.z + a1.w * b1.w;

    #pragma unroll
    for (int o = 8; o > 0; o >>= 1)
        v += __shfl_xor_sync(0xFFFFFFFFu, v, o);

    if (sub == 0)
        __stcs(&out[e], 1.0f / (1.0f + __expf(-v)));
}

// ---------------------------------------------------------------------------
// Launch. Identify inputs by element count (robust to metadata order).
// ---------------------------------------------------------------------------
extern "C" void kernel_launch(void* const* d_in, const int* in_sizes, int n_in,
                              void* d_out, int out_size)
{
    int i_xin = 0, i_xout = 1, i_ei = 2, i_w = 3;

    if (n_in == 4) {
        int w_idx = -1, ei_idx = -1;
        for (int i = 0; i < 4; i++)
            if (in_sizes[i] == D * D) w_idx = i;
        int idx[3], c = 0;
        for (int i = 0; i < 4; i++) if (i != w_idx) idx[c++] = i;
        if (w_idx >= 0 && c == 3) {
            if (in_sizes[idx[0]] == in_sizes[idx[1]])      { i_xin = idx[0]; i_xout = idx[1]; ei_idx = idx[2]; }
            else if (in_sizes[idx[0]] == in_sizes[idx[2]]) { i_xin = idx[0]; i_xout = idx[2]; ei_idx = idx[1]; }
            else                                            { i_xin = idx[1]; i_xout = idx[2]; ei_idx = idx[0]; }
            i_w = w_idx; i_ei = ei_idx;
        }
    }

    const float* x_in  = (const float*)d_in[i_xin];
    const float* x_out = (const float*)d_in[i_xout];
    const void*  ei    = d_in[i_ei];
    const float* W     = (const float*)d_in[i_w];
    float*       out   = (float*)d_out;

    int n = in_sizes[i_xin] / D;
    if (n > MAX_NODES) n = MAX_NODES;
    int E = in_sizes[i_ei] / 2;

    {
        dim3 grid((n + BM - 1) / BM);
        gemm_xout_w<<<grid, 512>>>(x_out, W, n);
    }

    detect_dtype<<<1, 256>>>((const unsigned int*)ei, in_sizes[i_ei] * 2);

    {
        long long total_threads = ((long long)E + 1) / 2 * 32;
        int blocks = (int)((total_threads + 255) / 256);
        edge_bilinear<<<blocks, 256>>>(x_in, ei, out, E);
    }
}